// round 12
// baseline (speedup 1.0000x reference)
#include <cuda_runtime.h>
#include <cuda_fp16.h>
#include <cstdint>

typedef unsigned long long ull;

#define TOKENS 32768
#define INDIM  512
#define CBK    8192
#define CBD    16
#define NTILES (CBK / 8)          // 1024 n-tiles of 8 codes
#define CHUNK_TILES 32            // tiles staged per chunk (256 codes)
#define NCHUNKS (NTILES / CHUNK_TILES)   // 32
#define CTA_TOKENS 64             // 2 warps x 32 tokens

// ---------------- device globals ----------------
__device__ __align__(16) float g_targets[TOKENS * CBD];   // 2 MB
__device__ __align__(16) uint4 g_Bpack[NTILES * 32];      // 512 KB: per-(tile,lane) fragment data
__device__ __align__(16) float g_c2[CBK];                 // 32 KB

// ---------------- helpers ----------------
__device__ __forceinline__ ull ffma2(ull a, ull b, ull c) {
    ull d; asm("fma.rn.f32x2 %0, %1, %2, %3;" : "=l"(d) : "l"(a), "l"(b), "l"(c)); return d;
}
__device__ __forceinline__ ull add2(ull a, ull b) {
    ull d; asm("add.rn.f32x2 %0, %1, %2;" : "=l"(d) : "l"(a), "l"(b)); return d;
}
__device__ __forceinline__ ull pack2(float lo, float hi) {
    ull d; asm("mov.b64 %0, {%1, %2};" : "=l"(d) : "f"(lo), "f"(hi)); return d;
}
__device__ __forceinline__ void unpack2(ull v, float& lo, float& hi) {
    asm("mov.b64 {%0, %1}, %2;" : "=f"(lo), "=f"(hi) : "l"(v));
}
__device__ __forceinline__ void cp16(uint32_t saddr, const void* g) {
    asm volatile("cp.async.cg.shared.global [%0], [%1], 16;" :: "r"(saddr), "l"(g));
}
__device__ __forceinline__ uint32_t packh2(__half a, __half b) {   // a -> low bits (even k)
    __half2 h = __halves2half2(a, b);
    return *reinterpret_cast<uint32_t*>(&h);
}
__device__ __forceinline__ void splitf(float v, __half& hi, __half& lo) {
    hi = __float2half_rn(v);
    lo = __float2half_rn(v - __half2float(hi));
}
__device__ __forceinline__ ull skey(float v, int idx) {
    unsigned u = __float_as_uint(v);
    u = (u & 0x80000000u) ? ~u : (u | 0x80000000u);
    return ((ull)u << 32) | (unsigned)idx;
}

#define MMA16816(d0,d1,d2,d3,a0,a1,a2,a3,b0,b1) \
    asm volatile("mma.sync.aligned.m16n8k16.row.col.f32.f16.f16.f32 " \
        "{%0,%1,%2,%3}, {%4,%5,%6,%7}, {%8,%9}, {%0,%1,%2,%3};" \
        : "+f"(d0), "+f"(d1), "+f"(d2), "+f"(d3) \
        : "r"(a0), "r"(a1), "r"(a2), "r"(a3), "r"(b0), "r"(b1))

// ---------------- kernel 0a: codebook norms ----------------
__global__ void kc2(const float* __restrict__ cb) {
    int n = blockIdx.x * 256 + threadIdx.x;
    if (n >= CBK) return;
    const float* c = cb + (size_t)n * CBD;
    float s = 0.f;
#pragma unroll
    for (int i = 0; i < CBD; ++i) s = fmaf(c[i], c[i], s);
    g_c2[n] = s;
}

// ---------------- kernel 0b: pack codebook into mma B-fragment layout ----------------
// B fragment (m16n8k16, col-major): lane l holds k = {2q, 2q+1, 2q+8, 2q+9}, n = l>>2, q = l&3
// uint4 per (tile,lane): x = hi(k0,k0+1), y = hi(k0+8,k0+9), z = lo(...), w = lo(...)
__global__ void kpack(const float* __restrict__ cb) {
    int id = blockIdx.x * 128 + threadIdx.x;     // (tile, lane)
    if (id >= NTILES * 32) return;
    int tile = id >> 5, l = id & 31;
    int n  = tile * 8 + (l >> 2);
    int k0 = (l & 3) * 2;
    const float* c = cb + (size_t)n * CBD;
    float v0 = c[k0], v1 = c[k0 + 1], v8 = c[k0 + 8], v9 = c[k0 + 9];
    __half h0, l0, h1, l1, h8, l8, h9, l9;
    splitf(v0, h0, l0); splitf(v1, h1, l1);
    splitf(v8, h8, l8); splitf(v9, h9, l9);
    uint4 o;
    o.x = packh2(h0, h1); o.y = packh2(h8, h9);
    o.z = packh2(l0, l1); o.w = packh2(l8, l9);
    g_Bpack[id] = o;
}

// ---------------- kernel 1: projection (proven R8 version) ----------------
__global__ void __launch_bounds__(128) k1(const float* __restrict__ in, const float* __restrict__ W) {
    __shared__ __align__(16) float sWt[INDIM * CBD];
    int tid = threadIdx.x;
    for (int idx = tid; idx < CBD * INDIM; idx += 128) {
        int j = idx >> 9;
        int d = idx & 511;
        sWt[d * CBD + j] = W[idx];
    }
    __syncthreads();

    int gt   = blockIdx.x * 128 + tid;
    int r    = gt >> 1;
    int half = gt & 1;

    const float4* xin = reinterpret_cast<const float4*>(in + (size_t)r * INDIM) + half * 64;
    ull acc[8];
#pragma unroll
    for (int k = 0; k < 8; ++k) acc[k] = 0ull;

#pragma unroll 2
    for (int d4 = 0; d4 < 64; ++d4) {
        float4 xv = xin[d4];
        float xs[4] = {xv.x, xv.y, xv.z, xv.w};
        int dbase = half * 256 + d4 * 4;
#pragma unroll
        for (int dd = 0; dd < 4; ++dd) {
            ull xd = pack2(xs[dd], xs[dd]);
            const ulonglong2* wd = reinterpret_cast<const ulonglong2*>(sWt + (dbase + dd) * CBD);
            ulonglong2 w0 = wd[0], w1 = wd[1], w2 = wd[2], w3 = wd[3];
            acc[0] = ffma2(w0.x, xd, acc[0]); acc[1] = ffma2(w0.y, xd, acc[1]);
            acc[2] = ffma2(w1.x, xd, acc[2]); acc[3] = ffma2(w1.y, xd, acc[3]);
            acc[4] = ffma2(w2.x, xd, acc[4]); acc[5] = ffma2(w2.y, xd, acc[5]);
            acc[6] = ffma2(w3.x, xd, acc[6]); acc[7] = ffma2(w3.y, xd, acc[7]);
        }
    }
#pragma unroll
    for (int k = 0; k < 8; ++k) {
        ull other = __shfl_xor_sync(0xFFFFFFFFu, acc[k], 1);
        acc[k] = add2(acc[k], other);
    }
    if (half == 0) {
        float4* out4 = reinterpret_cast<float4*>(g_targets + (size_t)r * CBD);
        float4 o;
        unpack2(acc[0], o.x, o.y); unpack2(acc[1], o.z, o.w); out4[0] = o;
        unpack2(acc[2], o.x, o.y); unpack2(acc[3], o.z, o.w); out4[1] = o;
        unpack2(acc[4], o.x, o.y); unpack2(acc[5], o.z, o.w); out4[2] = o;
        unpack2(acc[6], o.x, o.y); unpack2(acc[7], o.z, o.w); out4[3] = o;
    }
}

// ---------------- kernel 2: tensor-core (mma.sync) distance + argmin ----------------
// score[m][n] = c2[n] + sum_k (-2 t[m][k]) c[n][k], 4-product fp16-split (fp32-exact class)
__global__ void __launch_bounds__(64) kmma(float* __restrict__ out) {
    __shared__ __align__(16) uint4 sB[2][CHUNK_TILES * 32];   // 16 KB per buffer
    __shared__ __align__(16) float sC2[2][CHUNK_TILES * 8];   // 1 KB per buffer

    int tid  = threadIdx.x;
    int warp = tid >> 5;
    int l    = tid & 31;
    int r    = l >> 2;              // row within 8-row group
    int kq   = (l & 3) * 2;         // k / n sub-index
    int m0   = blockIdx.x * CTA_TOKENS + warp * 32;

    // ---- build A fragments in registers (once): -2t split into fp16 hi/lo ----
    // a0: (row r, k kq..kq+1) a1: (r+8, same) a2: (r, kq+8..9) a3: (r+8, same)
    uint32_t aH[2][4], aL[2][4];
#pragma unroll
    for (int T = 0; T < 2; ++T) {
#pragma unroll
        for (int hr = 0; hr < 2; ++hr) {
            const float* tp = g_targets + (size_t)(m0 + T * 16 + hr * 8 + r) * CBD;
            float v0 = -2.f * tp[kq],     v1 = -2.f * tp[kq + 1];
            float v8 = -2.f * tp[kq + 8], v9 = -2.f * tp[kq + 9];
            __half h0, w0, h1, w1, h8, w8, h9, w9;
            splitf(v0, h0, w0); splitf(v1, h1, w1);
            splitf(v8, h8, w8); splitf(v9, h9, w9);
            aH[T][hr]     = packh2(h0, h1);  aL[T][hr]     = packh2(w0, w1);
            aH[T][hr + 2] = packh2(h8, h9);  aL[T][hr + 2] = packh2(w8, w9);
        }
    }

    float best[4];
    int   bidx[4];
#pragma unroll
    for (int i = 0; i < 4; ++i) { best[i] = __int_as_float(0x7F800000); bidx[i] = 0; }

    auto stage = [&](int c, int buf) {
        const uint4* src = g_Bpack + (size_t)c * (CHUNK_TILES * 32);
        uint32_t sb = (uint32_t)__cvta_generic_to_shared(&sB[buf][0]);
        for (int k = tid; k < CHUNK_TILES * 32; k += 64)
            cp16(sb + k * 16, src + k);
        uint32_t sc = (uint32_t)__cvta_generic_to_shared(&sC2[buf][0]);
        const uint4* c2src = reinterpret_cast<const uint4*>(g_c2 + (size_t)c * (CHUNK_TILES * 8));
        if (tid < CHUNK_TILES * 8 / 4)
            cp16(sc + tid * 16, c2src + tid);
        asm volatile("cp.async.commit_group;" ::: "memory");
    };

    int buf = 0;
    stage(0, 0);
    for (int c = 0; c < NCHUNKS; ++c) {
        if (c + 1 < NCHUNKS) {
            stage(c + 1, buf ^ 1);
            asm volatile("cp.async.wait_group 1;" ::: "memory");
        } else {
            asm volatile("cp.async.wait_group 0;" ::: "memory");
        }
        __syncthreads();

        const uint4*  bp  = &sB[buf][0];
        const float*  c2p = &sC2[buf][0];
        int nbase = c * (CHUNK_TILES * 8);

#pragma unroll 2
        for (int t = 0; t < CHUNK_TILES; ++t) {
            uint4  q   = bp[t * 32 + l];
            float2 cc  = *reinterpret_cast<const float2*>(c2p + t * 8 + kq);
            int    n   = nbase + t * 8 + kq;

#pragma unroll
            for (int T = 0; T < 2; ++T) {
                float d0 = 0.f, d1 = 0.f, d2 = 0.f, d3 = 0.f;
                MMA16816(d0, d1, d2, d3, aH[T][0], aH[T][1], aH[T][2], aH[T][3], q.x, q.y);
                MMA16816(d0, d1, d2, d3, aH[T][0], aH[T][1], aH[T][2], aH[T][3], q.z, q.w);
                MMA16816(d0, d1, d2, d3, aL[T][0], aL[T][1], aL[T][2], aL[T][3], q.x, q.y);
                MMA16816(d0, d1, d2, d3, aL[T][0], aL[T][1], aL[T][2], aL[T][3], q.z, q.w);

                // d0:(row r, col n) d1:(r, n+1) d2:(r+8, n) d3:(r+8, n+1)
                int bi = T * 2;
                float v;
                v = d0 + cc.x; if (v < best[bi])     { best[bi]     = v; bidx[bi]     = n; }
                v = d1 + cc.y; if (v < best[bi])     { best[bi]     = v; bidx[bi]     = n + 1; }
                v = d2 + cc.x; if (v < best[bi + 1]) { best[bi + 1] = v; bidx[bi + 1] = n; }
                v = d3 + cc.y; if (v < best[bi + 1]) { best[bi + 1] = v; bidx[bi + 1] = n + 1; }
            }
        }
        __syncthreads();
        buf ^= 1;
    }

    // reduce across the 4 lanes sharing each row (lanes 4g..4g+3); u64-min keeps first index on ties
    ull k0 = skey(best[0], bidx[0]);
    ull k1v = skey(best[1], bidx[1]);
    ull k2v = skey(best[2], bidx[2]);
    ull k3v = skey(best[3], bidx[3]);
#pragma unroll
    for (int s = 1; s <= 2; s <<= 1) {
        ull o;
        o = __shfl_xor_sync(0xFFFFFFFFu, k0,  s); if (o < k0)  k0  = o;
        o = __shfl_xor_sync(0xFFFFFFFFu, k1v, s); if (o < k1v) k1v = o;
        o = __shfl_xor_sync(0xFFFFFFFFu, k2v, s); if (o < k2v) k2v = o;
        o = __shfl_xor_sync(0xFFFFFFFFu, k3v, s); if (o < k3v) k3v = o;
    }
    if ((l & 3) == 0) {
        out[m0 + r]      = (float)(unsigned)(k0  & 0xFFFFFFFFull);
        out[m0 + 8 + r]  = (float)(unsigned)(k1v & 0xFFFFFFFFull);
        out[m0 + 16 + r] = (float)(unsigned)(k2v & 0xFFFFFFFFull);
        out[m0 + 24 + r] = (float)(unsigned)(k3v & 0xFFFFFFFFull);
    }
}

// ---------------- launch ----------------
extern "C" void kernel_launch(void* const* d_in, const int* in_sizes, int n_in,
                              void* d_out, int out_size) {
    const float* in = nullptr;
    const float* W  = nullptr;
    const float* cb = nullptr;
    for (int i = 0; i < n_in; ++i) {
        if      (in_sizes[i] == TOKENS * INDIM) in = (const float*)d_in[i];
        else if (in_sizes[i] == CBD * INDIM)    W  = (const float*)d_in[i];
        else if (in_sizes[i] == CBK * CBD)      cb = (const float*)d_in[i];
    }
    if (!in) in = (const float*)d_in[0];
    if (!W)  W  = (const float*)d_in[1];
    if (!cb) cb = (const float*)d_in[2];
    float* out = (float*)d_out;

    kc2  <<<CBK / 256, 256>>>(cb);
    kpack<<<(NTILES * 32) / 128, 128>>>(cb);
    k1   <<<(TOKENS * 2) / 128, 128>>>(in, W);
    kmma <<<TOKENS / CTA_TOKENS, 64>>>(out);
}

// round 14
// speedup vs baseline: 1.5985x; 1.5985x over previous
#include <cuda_runtime.h>
#include <cuda_fp16.h>
#include <cstdint>

typedef unsigned long long ull;

#define TOKENS 32768
#define INDIM  512
#define CBK    8192
#define CBD    16
#define NTILES (CBK / 8)          // 1024 n-tiles of 8 codes
#define SPLITS 4
#define TILES_PER_SPLIT (NTILES / SPLITS)   // 256
#define CHUNK_TILES 32            // tiles staged per chunk (256 codes)
#define NCHUNKS (TILES_PER_SPLIT / CHUNK_TILES)   // 8
#define CTA_TOKENS 128            // 4 warps x 32 tokens

// ---------------- device globals ----------------
__device__ __align__(16) float g_targets[TOKENS * CBD];   // 2 MB
__device__ __align__(16) uint4 g_Bpack[NTILES * 32];      // 512 KB: per-(tile,lane) fragments
__device__ __align__(16) float g_c2[CBK];                 // 32 KB
__device__ ull g_packed[TOKENS];                          // sortable-key<<32 | idx

// ---------------- helpers ----------------
__device__ __forceinline__ ull ffma2(ull a, ull b, ull c) {
    ull d; asm("fma.rn.f32x2 %0, %1, %2, %3;" : "=l"(d) : "l"(a), "l"(b), "l"(c)); return d;
}
__device__ __forceinline__ ull add2(ull a, ull b) {
    ull d; asm("add.rn.f32x2 %0, %1, %2;" : "=l"(d) : "l"(a), "l"(b)); return d;
}
__device__ __forceinline__ ull pack2(float lo, float hi) {
    ull d; asm("mov.b64 %0, {%1, %2};" : "=l"(d) : "f"(lo), "f"(hi)); return d;
}
__device__ __forceinline__ void unpack2(ull v, float& lo, float& hi) {
    asm("mov.b64 {%0, %1}, %2;" : "=f"(lo), "=f"(hi) : "l"(v));
}
__device__ __forceinline__ void cp16(uint32_t saddr, const void* g) {
    asm volatile("cp.async.cg.shared.global [%0], [%1], 16;" :: "r"(saddr), "l"(g));
}
__device__ __forceinline__ uint32_t packh2(__half a, __half b) {   // a -> low bits (even k)
    __half2 h = __halves2half2(a, b);
    return *reinterpret_cast<uint32_t*>(&h);
}
__device__ __forceinline__ void splitf(float v, __half& hi, __half& lo) {
    hi = __float2half_rn(v);
    lo = __float2half_rn(v - __half2float(hi));
}
__device__ __forceinline__ ull skey(float v, int idx) {
    unsigned u = __float_as_uint(v);
    u = (u & 0x80000000u) ? ~u : (u | 0x80000000u);
    return ((ull)u << 32) | (unsigned)idx;
}

#define MMA16816(d0,d1,d2,d3,a0,a1,a2,a3,b0,b1) \
    asm volatile("mma.sync.aligned.m16n8k16.row.col.f32.f16.f16.f32 " \
        "{%0,%1,%2,%3}, {%4,%5,%6,%7}, {%8,%9}, {%0,%1,%2,%3};" \
        : "+f"(d0), "+f"(d1), "+f"(d2), "+f"(d3) \
        : "r"(a0), "r"(a1), "r"(a2), "r"(a3), "r"(b0), "r"(b1))

// ---------------- kernel 0a: codebook norms ----------------
__global__ void kc2(const float* __restrict__ cb) {
    int n = blockIdx.x * 256 + threadIdx.x;
    if (n >= CBK) return;
    const float* c = cb + (size_t)n * CBD;
    float s = 0.f;
#pragma unroll
    for (int i = 0; i < CBD; ++i) s = fmaf(c[i], c[i], s);
    g_c2[n] = s;
}

// ---------------- kernel 0b: pack codebook into mma B-fragment layout ----------------
// B frag (m16n8k16, col-major): lane l holds k = {2q, 2q+1, 2q+8, 2q+9}, n = l>>2, q = l&3
// uint4 per (tile,lane): x = hi(k0,k0+1), y = hi(k0+8,k0+9), z = lo(...), w = lo(...)
__global__ void kpack(const float* __restrict__ cb) {
    int id = blockIdx.x * 128 + threadIdx.x;     // (tile, lane)
    if (id >= NTILES * 32) return;
    int tile = id >> 5, l = id & 31;
    int n  = tile * 8 + (l >> 2);
    int k0 = (l & 3) * 2;
    const float* c = cb + (size_t)n * CBD;
    float v0 = c[k0], v1 = c[k0 + 1], v8 = c[k0 + 8], v9 = c[k0 + 9];
    __half h0, l0, h1, l1, h8, l8, h9, l9;
    splitf(v0, h0, l0); splitf(v1, h1, l1);
    splitf(v8, h8, l8); splitf(v9, h9, l9);
    uint4 o;
    o.x = packh2(h0, h1); o.y = packh2(h8, h9);
    o.z = packh2(l0, l1); o.w = packh2(l8, l9);
    g_Bpack[id] = o;
}

// ---------------- kernel 1: projection (proven; also inits g_packed) ----------------
__global__ void __launch_bounds__(128) k1(const float* __restrict__ in, const float* __restrict__ W) {
    __shared__ __align__(16) float sWt[INDIM * CBD];
    int tid = threadIdx.x;
    for (int idx = tid; idx < CBD * INDIM; idx += 128) {
        int j = idx >> 9;
        int d = idx & 511;
        sWt[d * CBD + j] = W[idx];
    }
    __syncthreads();

    int gt   = blockIdx.x * 128 + tid;
    int r    = gt >> 1;
    int half = gt & 1;
    if (half == 0) g_packed[r] = ~0ull;

    const float4* xin = reinterpret_cast<const float4*>(in + (size_t)r * INDIM) + half * 64;
    ull acc[8];
#pragma unroll
    for (int k = 0; k < 8; ++k) acc[k] = 0ull;

#pragma unroll 2
    for (int d4 = 0; d4 < 64; ++d4) {
        float4 xv = xin[d4];
        float xs[4] = {xv.x, xv.y, xv.z, xv.w};
        int dbase = half * 256 + d4 * 4;
#pragma unroll
        for (int dd = 0; dd < 4; ++dd) {
            ull xd = pack2(xs[dd], xs[dd]);
            const ulonglong2* wd = reinterpret_cast<const ulonglong2*>(sWt + (dbase + dd) * CBD);
            ulonglong2 w0 = wd[0], w1 = wd[1], w2 = wd[2], w3 = wd[3];
            acc[0] = ffma2(w0.x, xd, acc[0]); acc[1] = ffma2(w0.y, xd, acc[1]);
            acc[2] = ffma2(w1.x, xd, acc[2]); acc[3] = ffma2(w1.y, xd, acc[3]);
            acc[4] = ffma2(w2.x, xd, acc[4]); acc[5] = ffma2(w2.y, xd, acc[5]);
            acc[6] = ffma2(w3.x, xd, acc[6]); acc[7] = ffma2(w3.y, xd, acc[7]);
        }
    }
#pragma unroll
    for (int k = 0; k < 8; ++k) {
        ull other = __shfl_xor_sync(0xFFFFFFFFu, acc[k], 1);
        acc[k] = add2(acc[k], other);
    }
    if (half == 0) {
        float4* out4 = reinterpret_cast<float4*>(g_targets + (size_t)r * CBD);
        float4 o;
        unpack2(acc[0], o.x, o.y); unpack2(acc[1], o.z, o.w); out4[0] = o;
        unpack2(acc[2], o.x, o.y); unpack2(acc[3], o.z, o.w); out4[1] = o;
        unpack2(acc[4], o.x, o.y); unpack2(acc[5], o.z, o.w); out4[2] = o;
        unpack2(acc[6], o.x, o.y); unpack2(acc[7], o.z, o.w); out4[3] = o;
    }
}

// ---------------- kernel 2: mma.sync distance + argmin, 4-way codebook split ----------------
// score[m][n] = c2[n] + sum_k (-2 t[m][k]) c[n][k]  (4-product fp16 split)
__global__ void __launch_bounds__(128) kmma() {
    __shared__ __align__(16) uint4 sB[2][CHUNK_TILES * 32];   // 16 KB per buffer
    __shared__ __align__(16) float sC2[2][CHUNK_TILES * 8];   // 1 KB per buffer

    int tid   = threadIdx.x;
    int warp  = tid >> 5;
    int l     = tid & 31;
    int r     = l >> 2;              // row within 8-row group
    int kq    = (l & 3) * 2;         // k / n sub-index
    int split = blockIdx.x & (SPLITS - 1);
    int group = blockIdx.x >> 2;     // log2(SPLITS)=2
    int m0    = group * CTA_TOKENS + warp * 32;
    int tile0 = split * TILES_PER_SPLIT;

    // ---- A fragments in registers (once): -2t split into fp16 hi/lo ----
    uint32_t aH[2][4], aL[2][4];
#pragma unroll
    for (int T = 0; T < 2; ++T) {
#pragma unroll
        for (int hr = 0; hr < 2; ++hr) {
            const float* tp = g_targets + (size_t)(m0 + T * 16 + hr * 8 + r) * CBD;
            float v0 = -2.f * tp[kq],     v1 = -2.f * tp[kq + 1];
            float v8 = -2.f * tp[kq + 8], v9 = -2.f * tp[kq + 9];
            __half h0, w0, h1, w1, h8, w8, h9, w9;
            splitf(v0, h0, w0); splitf(v1, h1, w1);
            splitf(v8, h8, w8); splitf(v9, h9, w9);
            aH[T][hr]     = packh2(h0, h1);  aL[T][hr]     = packh2(w0, w1);
            aH[T][hr + 2] = packh2(h8, h9);  aL[T][hr + 2] = packh2(w8, w9);
        }
    }

    float best[4];
    int   bidx[4];
#pragma unroll
    for (int i = 0; i < 4; ++i) { best[i] = __int_as_float(0x7F800000); bidx[i] = 0; }

    auto stage = [&](int c, int buf) {
        const uint4* src = g_Bpack + (size_t)(tile0 + c * CHUNK_TILES) * 32;
        uint32_t sb = (uint32_t)__cvta_generic_to_shared(&sB[buf][0]);
        for (int k = tid; k < CHUNK_TILES * 32; k += 128)        // 1024 x 16B
            cp16(sb + k * 16, src + k);
        uint32_t sc = (uint32_t)__cvta_generic_to_shared(&sC2[buf][0]);
        const uint4* c2src = reinterpret_cast<const uint4*>(g_c2 + (size_t)(tile0 * 8) + c * (CHUNK_TILES * 8));
        if (tid < CHUNK_TILES * 8 / 4)                            // 64 x 16B
            cp16(sc + tid * 16, c2src + tid);
        asm volatile("cp.async.commit_group;" ::: "memory");
    };

    int buf = 0;
    stage(0, 0);
    for (int c = 0; c < NCHUNKS; ++c) {
        if (c + 1 < NCHUNKS) {
            stage(c + 1, buf ^ 1);
            asm volatile("cp.async.wait_group 1;" ::: "memory");
        } else {
            asm volatile("cp.async.wait_group 0;" ::: "memory");
        }
        __syncthreads();

        const uint4* bp  = &sB[buf][0];
        const float* c2p = &sC2[buf][0];
        int nbase = (tile0 + c * CHUNK_TILES) * 8;

#pragma unroll 2
        for (int t = 0; t < CHUNK_TILES; ++t) {
            uint4  q  = bp[t * 32 + l];
            float2 cc = *reinterpret_cast<const float2*>(c2p + t * 8 + kq);
            int    n  = nbase + t * 8 + kq;

#pragma unroll
            for (int T = 0; T < 2; ++T) {
                float d0 = 0.f, d1 = 0.f, d2 = 0.f, d3 = 0.f;
                MMA16816(d0, d1, d2, d3, aH[T][0], aH[T][1], aH[T][2], aH[T][3], q.x, q.y);
                MMA16816(d0, d1, d2, d3, aH[T][0], aH[T][1], aH[T][2], aH[T][3], q.z, q.w);
                MMA16816(d0, d1, d2, d3, aL[T][0], aL[T][1], aL[T][2], aL[T][3], q.x, q.y);
                MMA16816(d0, d1, d2, d3, aL[T][0], aL[T][1], aL[T][2], aL[T][3], q.z, q.w);

                // d0:(row r, col n) d1:(r, n+1) d2:(r+8, n) d3:(r+8, n+1)
                int bi = T * 2;
                float s0, s1, mn;
                s0 = d0 + cc.x; s1 = d1 + cc.y; mn = fminf(s0, s1);
                if (mn < best[bi]) { best[bi] = mn; bidx[bi] = (s0 <= mn) ? n : n + 1; }
                s0 = d2 + cc.x; s1 = d3 + cc.y; mn = fminf(s0, s1);
                if (mn < best[bi + 1]) { best[bi + 1] = mn; bidx[bi + 1] = (s0 <= mn) ? n : n + 1; }
            }
        }
        __syncthreads();
        buf ^= 1;
    }

    // reduce across the 4 lanes sharing each row; u64-min keeps first index on ties
    ull k0  = skey(best[0], bidx[0]);
    ull k1v = skey(best[1], bidx[1]);
    ull k2v = skey(best[2], bidx[2]);
    ull k3v = skey(best[3], bidx[3]);
#pragma unroll
    for (int s = 1; s <= 2; s <<= 1) {
        ull o;
        o = __shfl_xor_sync(0xFFFFFFFFu, k0,  s); if (o < k0)  k0  = o;
        o = __shfl_xor_sync(0xFFFFFFFFu, k1v, s); if (o < k1v) k1v = o;
        o = __shfl_xor_sync(0xFFFFFFFFu, k2v, s); if (o < k2v) k2v = o;
        o = __shfl_xor_sync(0xFFFFFFFFu, k3v, s); if (o < k3v) k3v = o;
    }
    if ((l & 3) == 0) {
        atomicMin(&g_packed[m0 + r],      k0);
        atomicMin(&g_packed[m0 + 8 + r],  k1v);
        atomicMin(&g_packed[m0 + 16 + r], k2v);
        atomicMin(&g_packed[m0 + 24 + r], k3v);
    }
}

// ---------------- kernel 3: extract labels as float32 ----------------
__global__ void kfin(float* __restrict__ out) {
    int i = blockIdx.x * blockDim.x + threadIdx.x;
    if (i < TOKENS) out[i] = (float)(unsigned)(g_packed[i] & 0xFFFFFFFFull);
}

// ---------------- launch ----------------
extern "C" void kernel_launch(void* const* d_in, const int* in_sizes, int n_in,
                              void* d_out, int out_size) {
    const float* in = nullptr;
    const float* W  = nullptr;
    const float* cb = nullptr;
    for (int i = 0; i < n_in; ++i) {
        if      (in_sizes[i] == TOKENS * INDIM) in = (const float*)d_in[i];
        else if (in_sizes[i] == CBD * INDIM)    W  = (const float*)d_in[i];
        else if (in_sizes[i] == CBK * CBD)      cb = (const float*)d_in[i];
    }
    if (!in) in = (const float*)d_in[0];
    if (!W)  W  = (const float*)d_in[1];
    if (!cb) cb = (const float*)d_in[2];
    float* out = (float*)d_out;

    kc2  <<<CBK / 256, 256>>>(cb);
    kpack<<<(NTILES * 32) / 128, 128>>>(cb);
    k1   <<<(TOKENS * 2) / 128, 128>>>(in, W);
    kmma <<<(TOKENS / CTA_TOKENS) * SPLITS, 128>>>();
    kfin <<<TOKENS / 256, 256>>>(out);
}

// round 15
// speedup vs baseline: 1.6768x; 1.0490x over previous
#include <cuda_runtime.h>
#include <cuda_fp16.h>
#include <cstdint>

typedef unsigned long long ull;

#define TOKENS 32768
#define INDIM  512
#define CBK    8192
#define CBD    16
#define NTILES (CBK / 8)          // 1024 n-tiles of 8 codes
#define SPLITS 4
#define TILES_PER_SPLIT (NTILES / SPLITS)   // 256
#define CHUNK_TILES 32            // tiles staged per chunk (256 codes)
#define NCHUNKS (TILES_PER_SPLIT / CHUNK_TILES)   // 8
#define CTA_TOKENS 128            // 4 warps x 32 tokens
#define PACK_BLOCKS 256           // NTILES*32/128
#define PROJ_BLOCKS 512           // TOKENS*2/128

// ---------------- device globals ----------------
__device__ __align__(16) float g_targets[TOKENS * CBD];   // 2 MB
__device__ __align__(16) uint4 g_Bpack[NTILES * 32];      // 512 KB per-(tile,lane) fragments
__device__ __align__(16) float g_c2[CBK];                 // 32 KB
__device__ ull g_packed[TOKENS];                          // sortable-key<<32 | idx

// ---------------- helpers ----------------
__device__ __forceinline__ ull ffma2(ull a, ull b, ull c) {
    ull d; asm("fma.rn.f32x2 %0, %1, %2, %3;" : "=l"(d) : "l"(a), "l"(b), "l"(c)); return d;
}
__device__ __forceinline__ ull add2(ull a, ull b) {
    ull d; asm("add.rn.f32x2 %0, %1, %2;" : "=l"(d) : "l"(a), "l"(b)); return d;
}
__device__ __forceinline__ ull pack2(float lo, float hi) {
    ull d; asm("mov.b64 %0, {%1, %2};" : "=l"(d) : "f"(lo), "f"(hi)); return d;
}
__device__ __forceinline__ void unpack2(ull v, float& lo, float& hi) {
    asm("mov.b64 {%0, %1}, %2;" : "=f"(lo), "=f"(hi) : "l"(v));
}
__device__ __forceinline__ void cp16(uint32_t saddr, const void* g) {
    asm volatile("cp.async.cg.shared.global [%0], [%1], 16;" :: "r"(saddr), "l"(g));
}
__device__ __forceinline__ uint32_t packh2(__half a, __half b) {   // a -> low bits (even k)
    __half2 h = __halves2half2(a, b);
    return *reinterpret_cast<uint32_t*>(&h);
}
__device__ __forceinline__ void splitf(float v, __half& hi, __half& lo) {
    hi = __float2half_rn(v);
    lo = __float2half_rn(v - __half2float(hi));
}
__device__ __forceinline__ ull skey(float v, int idx) {
    unsigned u = __float_as_uint(v);
    u = (u & 0x80000000u) ? ~u : (u | 0x80000000u);
    return ((ull)u << 32) | (unsigned)idx;
}

#define MMA16816(d0,d1,d2,d3,a0,a1,a2,a3,b0,b1) \
    asm volatile("mma.sync.aligned.m16n8k16.row.col.f32.f16.f16.f32 " \
        "{%0,%1,%2,%3}, {%4,%5,%6,%7}, {%8,%9}, {%0,%1,%2,%3};" \
        : "+f"(d0), "+f"(d1), "+f"(d2), "+f"(d3) \
        : "r"(a0), "r"(a1), "r"(a2), "r"(a3), "r"(b0), "r"(b1))

// ---------------- fused prep: pack+norms (blocks 0..255) | projection (blocks 256..767) ----------------
__global__ void __launch_bounds__(128) kprep(const float* __restrict__ in,
                                             const float* __restrict__ W,
                                             const float* __restrict__ cb) {
    __shared__ __align__(16) float sWt[INDIM * CBD];   // used by projection branch only
    int tid = threadIdx.x;

    if (blockIdx.x < PACK_BLOCKS) {
        // ---- codebook pack into B-fragment layout + norms ----
        // B frag (m16n8k16 col-major): lane l holds k = {2q,2q+1,2q+8,2q+9}, n = l>>2, q = l&3
        int id   = blockIdx.x * 128 + tid;             // (tile, lane)
        int tile = id >> 5, l = id & 31;
        int n  = tile * 8 + (l >> 2);
        int k0 = (l & 3) * 2;
        const float* c = cb + (size_t)n * CBD;
        float v0 = c[k0], v1 = c[k0 + 1], v8 = c[k0 + 8], v9 = c[k0 + 9];
        __half h0, l0, h1, l1, h8, l8, h9, l9;
        splitf(v0, h0, l0); splitf(v1, h1, l1);
        splitf(v8, h8, l8); splitf(v9, h9, l9);
        uint4 o;
        o.x = packh2(h0, h1); o.y = packh2(h8, h9);
        o.z = packh2(l0, l1); o.w = packh2(l8, l9);
        g_Bpack[id] = o;
        if ((l & 3) == 0) {        // one lane per code computes the norm (L1-hot rereads)
            float s = 0.f;
#pragma unroll
            for (int i = 0; i < CBD; ++i) s = fmaf(c[i], c[i], s);
            g_c2[n] = s;
        }
        return;
    }

    // ---- projection: 2 threads per row, f32x2 (proven); also inits g_packed ----
    for (int idx = tid; idx < CBD * INDIM; idx += 128) {
        int j = idx >> 9;
        int d = idx & 511;
        sWt[d * CBD + j] = W[idx];
    }
    __syncthreads();

    int gt   = (blockIdx.x - PACK_BLOCKS) * 128 + tid;
    int r    = gt >> 1;
    int half = gt & 1;
    if (half == 0) g_packed[r] = ~0ull;

    const float4* xin = reinterpret_cast<const float4*>(in + (size_t)r * INDIM) + half * 64;
    ull acc[8];
#pragma unroll
    for (int k = 0; k < 8; ++k) acc[k] = 0ull;

#pragma unroll 2
    for (int d4 = 0; d4 < 64; ++d4) {
        float4 xv = xin[d4];
        float xs[4] = {xv.x, xv.y, xv.z, xv.w};
        int dbase = half * 256 + d4 * 4;
#pragma unroll
        for (int dd = 0; dd < 4; ++dd) {
            ull xd = pack2(xs[dd], xs[dd]);
            const ulonglong2* wd = reinterpret_cast<const ulonglong2*>(sWt + (dbase + dd) * CBD);
            ulonglong2 w0 = wd[0], w1 = wd[1], w2 = wd[2], w3 = wd[3];
            acc[0] = ffma2(w0.x, xd, acc[0]); acc[1] = ffma2(w0.y, xd, acc[1]);
            acc[2] = ffma2(w1.x, xd, acc[2]); acc[3] = ffma2(w1.y, xd, acc[3]);
            acc[4] = ffma2(w2.x, xd, acc[4]); acc[5] = ffma2(w2.y, xd, acc[5]);
            acc[6] = ffma2(w3.x, xd, acc[6]); acc[7] = ffma2(w3.y, xd, acc[7]);
        }
    }
#pragma unroll
    for (int k = 0; k < 8; ++k) {
        ull other = __shfl_xor_sync(0xFFFFFFFFu, acc[k], 1);
        acc[k] = add2(acc[k], other);
    }
    if (half == 0) {
        float4* out4 = reinterpret_cast<float4*>(g_targets + (size_t)r * CBD);
        float4 o;
        unpack2(acc[0], o.x, o.y); unpack2(acc[1], o.z, o.w); out4[0] = o;
        unpack2(acc[2], o.x, o.y); unpack2(acc[3], o.z, o.w); out4[1] = o;
        unpack2(acc[4], o.x, o.y); unpack2(acc[5], o.z, o.w); out4[2] = o;
        unpack2(acc[6], o.x, o.y); unpack2(acc[7], o.z, o.w); out4[3] = o;
    }
}

// ---------------- kernel 2: mma.sync distance + argmin, split accumulator chains ----------------
// score[m][n] = c2[n] + sum_k (-2 t[m][k]) c[n][k]  (4-product fp16 split, 2 chains of depth 2)
__global__ void __launch_bounds__(128) kmma() {
    __shared__ __align__(16) uint4 sB[2][CHUNK_TILES * 32];   // 16 KB per buffer
    __shared__ __align__(16) float sC2[2][CHUNK_TILES * 8];   // 1 KB per buffer

    int tid   = threadIdx.x;
    int warp  = tid >> 5;
    int l     = tid & 31;
    int r     = l >> 2;              // row within 8-row group
    int kq    = (l & 3) * 2;         // k / n sub-index
    int split = blockIdx.x & (SPLITS - 1);
    int group = blockIdx.x >> 2;
    int m0    = group * CTA_TOKENS + warp * 32;
    int tile0 = split * TILES_PER_SPLIT;

    // ---- A fragments in registers (once): -2t split into fp16 hi/lo ----
    uint32_t aH[2][4], aL[2][4];
#pragma unroll
    for (int T = 0; T < 2; ++T) {
#pragma unroll
        for (int hr = 0; hr < 2; ++hr) {
            const float* tp = g_targets + (size_t)(m0 + T * 16 + hr * 8 + r) * CBD;
            float v0 = -2.f * tp[kq],     v1 = -2.f * tp[kq + 1];
            float v8 = -2.f * tp[kq + 8], v9 = -2.f * tp[kq + 9];
            __half h0, w0, h1, w1, h8, w8, h9, w9;
            splitf(v0, h0, w0); splitf(v1, h1, w1);
            splitf(v8, h8, w8); splitf(v9, h9, w9);
            aH[T][hr]     = packh2(h0, h1);  aL[T][hr]     = packh2(w0, w1);
            aH[T][hr + 2] = packh2(h8, h9);  aL[T][hr + 2] = packh2(w8, w9);
        }
    }

    float best[4];
    int   bidx[4];
#pragma unroll
    for (int i = 0; i < 4; ++i) { best[i] = __int_as_float(0x7F800000); bidx[i] = 0; }

    auto stage = [&](int c, int buf) {
        const uint4* src = g_Bpack + (size_t)(tile0 + c * CHUNK_TILES) * 32;
        uint32_t sb = (uint32_t)__cvta_generic_to_shared(&sB[buf][0]);
        for (int k = tid; k < CHUNK_TILES * 32; k += 128)        // 1024 x 16B
            cp16(sb + k * 16, src + k);
        uint32_t sc = (uint32_t)__cvta_generic_to_shared(&sC2[buf][0]);
        const uint4* c2src = reinterpret_cast<const uint4*>(g_c2 + (size_t)(tile0 * 8) + c * (CHUNK_TILES * 8));
        if (tid < CHUNK_TILES * 8 / 4)                            // 64 x 16B
            cp16(sc + tid * 16, c2src + tid);
        asm volatile("cp.async.commit_group;" ::: "memory");
    };

    int buf = 0;
    stage(0, 0);
    for (int c = 0; c < NCHUNKS; ++c) {
        if (c + 1 < NCHUNKS) {
            stage(c + 1, buf ^ 1);
            asm volatile("cp.async.wait_group 1;" ::: "memory");
        } else {
            asm volatile("cp.async.wait_group 0;" ::: "memory");
        }
        __syncthreads();

        const uint4* bp  = &sB[buf][0];
        const float* c2p = &sC2[buf][0];
        int nbase = (tile0 + c * CHUNK_TILES) * 8;

#pragma unroll 2
        for (int t = 0; t < CHUNK_TILES; ++t) {
            uint4  q  = bp[t * 32 + l];
            float2 cc = *reinterpret_cast<const float2*>(c2p + t * 8 + kq);
            int    n  = nbase + t * 8 + kq;

#pragma unroll
            for (int T = 0; T < 2; ++T) {
                // chain d: c2-init + hi*hi + hi*lo ; chain e: lo*hi + lo*lo (depth 2 each)
                float d0 = cc.x, d1 = cc.y, d2 = cc.x, d3 = cc.y;
                float e0 = 0.f,  e1 = 0.f,  e2 = 0.f,  e3 = 0.f;
                MMA16816(d0, d1, d2, d3, aH[T][0], aH[T][1], aH[T][2], aH[T][3], q.x, q.y);
                MMA16816(e0, e1, e2, e3, aL[T][0], aL[T][1], aL[T][2], aL[T][3], q.x, q.y);
                MMA16816(d0, d1, d2, d3, aH[T][0], aH[T][1], aH[T][2], aH[T][3], q.z, q.w);
                MMA16816(e0, e1, e2, e3, aL[T][0], aL[T][1], aL[T][2], aL[T][3], q.z, q.w);

                float s0 = d0 + e0, s1 = d1 + e1, s2 = d2 + e2, s3 = d3 + e3;
                // s0:(row r, col n) s1:(r, n+1) s2:(r+8, n) s3:(r+8, n+1)
                int bi = T * 2;
                float mn;
                mn = fminf(s0, s1);
                if (mn < best[bi])     { best[bi]     = mn; bidx[bi]     = (s0 <= mn) ? n : n + 1; }
                mn = fminf(s2, s3);
                if (mn < best[bi + 1]) { best[bi + 1] = mn; bidx[bi + 1] = (s2 <= mn) ? n : n + 1; }
            }
        }
        __syncthreads();
        buf ^= 1;
    }

    // reduce across the 4 lanes sharing each row; u64-min keeps first index on ties
    ull k0  = skey(best[0], bidx[0]);
    ull k1v = skey(best[1], bidx[1]);
    ull k2v = skey(best[2], bidx[2]);
    ull k3v = skey(best[3], bidx[3]);
#pragma unroll
    for (int s = 1; s <= 2; s <<= 1) {
        ull o;
        o = __shfl_xor_sync(0xFFFFFFFFu, k0,  s); if (o < k0)  k0  = o;
        o = __shfl_xor_sync(0xFFFFFFFFu, k1v, s); if (o < k1v) k1v = o;
        o = __shfl_xor_sync(0xFFFFFFFFu, k2v, s); if (o < k2v) k2v = o;
        o = __shfl_xor_sync(0xFFFFFFFFu, k3v, s); if (o < k3v) k3v = o;
    }
    if ((l & 3) == 0) {
        atomicMin(&g_packed[m0 + r],      k0);
        atomicMin(&g_packed[m0 + 8 + r],  k1v);
        atomicMin(&g_packed[m0 + 16 + r], k2v);
        atomicMin(&g_packed[m0 + 24 + r], k3v);
    }
}

// ---------------- kernel 3: extract labels as float32 ----------------
__global__ void kfin(float* __restrict__ out) {
    int i = blockIdx.x * blockDim.x + threadIdx.x;
    if (i < TOKENS) out[i] = (float)(unsigned)(g_packed[i] & 0xFFFFFFFFull);
}

// ---------------- launch ----------------
extern "C" void kernel_launch(void* const* d_in, const int* in_sizes, int n_in,
                              void* d_out, int out_size) {
    const float* in = nullptr;
    const float* W  = nullptr;
    const float* cb = nullptr;
    for (int i = 0; i < n_in; ++i) {
        if      (in_sizes[i] == TOKENS * INDIM) in = (const float*)d_in[i];
        else if (in_sizes[i] == CBD * INDIM)    W  = (const float*)d_in[i];
        else if (in_sizes[i] == CBK * CBD)      cb = (const float*)d_in[i];
    }
    if (!in) in = (const float*)d_in[0];
    if (!W)  W  = (const float*)d_in[1];
    if (!cb) cb = (const float*)d_in[2];
    float* out = (float*)d_out;

    kprep<<<PACK_BLOCKS + PROJ_BLOCKS, 128>>>(in, W, cb);
    kmma <<<(TOKENS / CTA_TOKENS) * SPLITS, 128>>>();
    kfin <<<TOKENS / 256, 256>>>(out);
}